// round 2
// baseline (speedup 1.0000x reference)
#include <cuda_runtime.h>
#include <cuda_bf16.h>
#include <cstdint>

// Problem constants (from reference): E=4194304, DIN=DOUT=8.
// d_in[0] = values     f32 [1048576, 8]
// d_in[1] = weights    f32 [65536, 8, 8]
// d_in[2] = input_idx  i32 [E]
// d_in[3] = weight_idx i32 [E]
// out     = f32 [E, 8]
//
// One thread per (edge, out_row). lane%8 = out row o; 8 lanes share one edge.
// Warp covers 4 edges: W loads = 4 contiguous 256B blocks, x loads merge
// (same address across 8 lanes), output store fully coalesced 128B/warp.

__global__ __launch_bounds__(256) void edge_mm_kernel(
    const float4* __restrict__ values,    // [NUM_VALUES*2] float4
    const float4* __restrict__ weights,   // [NUM_WEIGHTS*16] float4
    const int*    __restrict__ input_idx,
    const int*    __restrict__ weight_idx,
    float*        __restrict__ out,
    int E)
{
    int tid = blockIdx.x * blockDim.x + threadIdx.x;
    int e = tid >> 3;
    if (e >= E) return;
    int o = tid & 7;

    int vi = __ldg(input_idx + e);
    int wi = __ldg(weight_idx + e);

    // x row: 32B at values + vi*32B
    float4 x0 = values[vi * 2 + 0];
    float4 x1 = values[vi * 2 + 1];

    // w row o: 32B at weights + wi*256B + o*32B
    float4 w0 = weights[wi * 16 + o * 2 + 0];
    float4 w1 = weights[wi * 16 + o * 2 + 1];

    float y = w0.x * x0.x;
    y = fmaf(w0.y, x0.y, y);
    y = fmaf(w0.z, x0.z, y);
    y = fmaf(w0.w, x0.w, y);
    y = fmaf(w1.x, x1.x, y);
    y = fmaf(w1.y, x1.y, y);
    y = fmaf(w1.z, x1.z, y);
    y = fmaf(w1.w, x1.w, y);

    out[tid] = y;
}

extern "C" void kernel_launch(void* const* d_in, const int* in_sizes, int n_in,
                              void* d_out, int out_size)
{
    const float4* values  = (const float4*)d_in[0];
    const float4* weights = (const float4*)d_in[1];
    const int* input_idx  = (const int*)d_in[2];
    const int* weight_idx = (const int*)d_in[3];
    float* out = (float*)d_out;

    int E = in_sizes[2];              // element count of input_idx
    int total = E * 8;                // one thread per output element
    int threads = 256;
    int blocks = (total + threads - 1) / threads;

    edge_mm_kernel<<<blocks, threads>>>(values, weights, input_idx, weight_idx,
                                        out, E);
}

// round 3
// speedup vs baseline: 1.5289x; 1.5289x over previous
#include <cuda_runtime.h>
#include <cuda_bf16.h>
#include <cstdint>

// d_in[0] = values     f32 [1048576, 8]
// d_in[1] = weights    f32 [65536, 8, 8]
// d_in[2] = input_idx  i32 [E]
// d_in[3] = weight_idx i32 [E]
// out     = f32 [E, 8]
//
// 8 lanes cooperate per edge; each thread handles 2 edges (e0=g, e1=g+E/2).
// Lane k loads W float4 #k and #(k+8) -> every LDG.128 covers full 128B lines.
// Lane k loads only x half (k&1). Partial dot products are combined across
// lane pairs with shfl_xor(1); each lane then owns one distinct output element:
//   chunk0 pair-sum = y[k>>1], chunk1 pair-sum = y[(k>>1)+4]
//   even lane keeps chunk0 result at pos k>>1, odd lane chunk1 at (k>>1)+4.

__device__ __forceinline__ float dot4(float4 a, float4 b) {
    float r = a.x * b.x;
    r = fmaf(a.y, b.y, r);
    r = fmaf(a.z, b.z, r);
    r = fmaf(a.w, b.w, r);
    return r;
}

__global__ __launch_bounds__(256) void edge_mm_kernel(
    const float4* __restrict__ values,    // [NUM_VALUES*2]  float4
    const float4* __restrict__ weights,   // [NUM_WEIGHTS*16] float4
    const int*    __restrict__ input_idx,
    const int*    __restrict__ weight_idx,
    float*        __restrict__ out,
    int half_E)
{
    int tid = blockIdx.x * blockDim.x + threadIdx.x;
    int g = tid >> 3;           // edge-pair group
    if (g >= half_E) return;
    int k = tid & 7;            // lane role within edge
    int half = k & 1;

    int e0 = g;
    int e1 = g + half_E;

    // Indices (8-lane duplicated, but contiguous across the warp: ~1 wf each)
    int vi0 = __ldg(input_idx + e0);
    int vi1 = __ldg(input_idx + e1);
    int wi0 = __ldg(weight_idx + e0);
    int wi1 = __ldg(weight_idx + e1);

    // x halves: 16B per thread, both W chunks reuse it
    float4 xa = values[vi0 * 2 + half];
    float4 xb = values[vi1 * 2 + half];

    // W quarter-rows: float4 #k = (row k>>1, cols half*4..), #(k+8) = row (k>>1)+4
    const float4* W0 = weights + wi0 * 16;
    const float4* W1 = weights + wi1 * 16;
    float4 wa0 = W0[k];
    float4 wa1 = W0[k + 8];
    float4 wb0 = W1[k];
    float4 wb1 = W1[k + 8];

    float pa0 = dot4(wa0, xa);
    float pa1 = dot4(wa1, xa);
    float pb0 = dot4(wb0, xb);
    float pb1 = dot4(wb1, xb);

    // Pair-sum across halves
    pa0 += __shfl_xor_sync(0xFFFFFFFFu, pa0, 1);
    pa1 += __shfl_xor_sync(0xFFFFFFFFu, pa1, 1);
    pb0 += __shfl_xor_sync(0xFFFFFFFFu, pb0, 1);
    pb1 += __shfl_xor_sync(0xFFFFFFFFu, pb1, 1);

    int pos = (k >> 1) + (half << 2);
    float ya = half ? pa1 : pa0;
    float yb = half ? pb1 : pb0;

    out[e0 * 8 + pos] = ya;
    out[e1 * 8 + pos] = yb;
}

extern "C" void kernel_launch(void* const* d_in, const int* in_sizes, int n_in,
                              void* d_out, int out_size)
{
    const float4* values  = (const float4*)d_in[0];
    const float4* weights = (const float4*)d_in[1];
    const int* input_idx  = (const int*)d_in[2];
    const int* weight_idx = (const int*)d_in[3];
    float* out = (float*)d_out;

    int E = in_sizes[2];
    int half_E = E >> 1;               // E is even (4194304)
    long long total = (long long)half_E * 8;
    int threads = 256;
    int blocks = (int)((total + threads - 1) / threads);

    edge_mm_kernel<<<blocks, threads>>>(values, weights, input_idx, weight_idx,
                                        out, half_E);
}